// round 1
// baseline (speedup 1.0000x reference)
#include <cuda_runtime.h>
#include <cstddef>

#define NN 50000
#define EE 800000
#define NF 256
#define HH 128
#define LL 3
#define NEG_SLOPE 0.01f

// ---------------- scratch (no allocations allowed) ----------------
__device__ float g_h0 [(size_t)NN * HH];   // projected node features (pre-fusion)
__device__ float g_cur[(size_t)NN * HH];   // current hidden h
__device__ float g_hs [(size_t)NN * HH];   // h * invdeg
__device__ float g_agg[(size_t)NN * HH];   // aggregation buffer
__device__ float g_colsum[HH * (LL + 1)];  // column sums of the stack

// ---------------- zero init ----------------
__global__ void zero_kernel(float* __restrict__ a, int n4, float* __restrict__ cs) {
    int i = blockIdx.x * blockDim.x + threadIdx.x;
    if (i < n4) reinterpret_cast<float4*>(a)[i] = make_float4(0.f, 0.f, 0.f, 0.f);
    if (i < HH * (LL + 1)) cs[i] = 0.f;
}

// ---------------- GEMM: C[M,128] = A[M,K] @ W[K,128] + bias, optional leaky,
// and accumulate per-column sums into colsum[colsum_off..] ----------------
template <int K, bool LEAKY>
__global__ __launch_bounds__(256)
void gemm_kernel(const float* __restrict__ A, const float* __restrict__ W,
                 const float* __restrict__ bias, float* __restrict__ C,
                 float* __restrict__ colsum, int colsum_off) {
    __shared__ float As[16][132];   // k-major, padded
    __shared__ float Ws[16][128];
    __shared__ float Scol[16][128];

    const int tid = threadIdx.x;
    const int ty = tid >> 4;   // 0..15 row group
    const int tx = tid & 15;   // 0..15 col group
    const int row0 = blockIdx.x * 128;

    float acc[8][8];
#pragma unroll
    for (int i = 0; i < 8; i++)
#pragma unroll
        for (int j = 0; j < 8; j++) acc[i][j] = 0.f;

    for (int k0 = 0; k0 < K; k0 += 16) {
        // A tile: 128 rows x 16 k  (512 float4 loads, 2 per thread)
#pragma unroll
        for (int t = 0; t < 2; t++) {
            int f = tid + t * 256;
            int m = f >> 2;
            int q = f & 3;
            float4 v = make_float4(0.f, 0.f, 0.f, 0.f);
            int r = row0 + m;
            if (r < NN)
                v = *reinterpret_cast<const float4*>(A + (size_t)r * K + k0 + q * 4);
            As[q * 4 + 0][m] = v.x;
            As[q * 4 + 1][m] = v.y;
            As[q * 4 + 2][m] = v.z;
            As[q * 4 + 3][m] = v.w;
        }
        // W tile: 16 x 128
#pragma unroll
        for (int t = 0; t < 2; t++) {
            int f = tid + t * 256;
            int kk = f >> 5;
            int c4 = f & 31;
            float4 w = *reinterpret_cast<const float4*>(W + (size_t)(k0 + kk) * HH + c4 * 4);
            *reinterpret_cast<float4*>(&Ws[kk][c4 * 4]) = w;
        }
        __syncthreads();
#pragma unroll
        for (int kk = 0; kk < 16; kk++) {
            float a[8], b[8];
            *reinterpret_cast<float4*>(&a[0]) = *reinterpret_cast<const float4*>(&As[kk][ty * 8]);
            *reinterpret_cast<float4*>(&a[4]) = *reinterpret_cast<const float4*>(&As[kk][ty * 8 + 4]);
            *reinterpret_cast<float4*>(&b[0]) = *reinterpret_cast<const float4*>(&Ws[kk][tx * 8]);
            *reinterpret_cast<float4*>(&b[4]) = *reinterpret_cast<const float4*>(&Ws[kk][tx * 8 + 4]);
#pragma unroll
            for (int i = 0; i < 8; i++)
#pragma unroll
                for (int j = 0; j < 8; j++) acc[i][j] += a[i] * b[j];
        }
        __syncthreads();
    }

    // epilogue: bias, activation, store, per-column partial sums
    float bs[8];
#pragma unroll
    for (int j = 0; j < 8; j++) bs[j] = bias[tx * 8 + j];

    float csum[8];
#pragma unroll
    for (int j = 0; j < 8; j++) csum[j] = 0.f;

#pragma unroll
    for (int i = 0; i < 8; i++) {
        int row = row0 + ty * 8 + i;
        if (row < NN) {
            float v[8];
#pragma unroll
            for (int j = 0; j < 8; j++) {
                float x = acc[i][j] + bs[j];
                if (LEAKY) x = (x >= 0.f) ? x : NEG_SLOPE * x;
                v[j] = x;
                csum[j] += x;
            }
            float4* dst = reinterpret_cast<float4*>(C + (size_t)row * HH + tx * 8);
            dst[0] = make_float4(v[0], v[1], v[2], v[3]);
            dst[1] = make_float4(v[4], v[5], v[6], v[7]);
        }
    }
    __syncthreads();
#pragma unroll
    for (int j = 0; j < 8; j++) Scol[ty][tx * 8 + j] = csum[j];
    __syncthreads();
    if (tid < 128) {
        float s = 0.f;
#pragma unroll
        for (int t = 0; t < 16; t++) s += Scol[t][tid];
        atomicAdd(&colsum[colsum_off + tid], s);
    }
}

// ---------------- edge scatter: out[dst] += msg[src], one warp per edge ----------------
__global__ __launch_bounds__(256)
void scatter_kernel(const float* __restrict__ msg, float* __restrict__ out,
                    const int* __restrict__ src, const int* __restrict__ dst) {
    int warp = (blockIdx.x * blockDim.x + threadIdx.x) >> 5;
    int lane = threadIdx.x & 31;
    if (warp >= EE) return;
    int s = __ldg(src + warp);
    int d = __ldg(dst + warp);
    float4 v = *reinterpret_cast<const float4*>(msg + (size_t)s * HH + lane * 4);
    atomicAdd(reinterpret_cast<float4*>(out + (size_t)d * HH + lane * 4), v);
}

// ---------------- prep: hs = cur * invdeg ; agg = cur ----------------
__global__ __launch_bounds__(256)
void prep_kernel(const float* __restrict__ cur, const float* __restrict__ degree,
                 float* __restrict__ hs, float* __restrict__ agg) {
    int i = blockIdx.x * blockDim.x + threadIdx.x;   // float4 index
    const int n4 = NN * HH / 4;
    if (i >= n4) return;
    int node = i >> 5;  // 32 float4 per node
    float inv = 1.0f / __ldg(degree + node);
    float4 v = reinterpret_cast<const float4*>(cur)[i];
    reinterpret_cast<float4*>(agg)[i] = v;
    float4 w = make_float4(v.x * inv, v.y * inv, v.z * inv, v.w * inv);
    reinterpret_cast<float4*>(hs)[i] = w;
}

// ---------------- final: column means -> Wpred -> Wcls -> softmax ----------------
__global__ void final_kernel(const float* __restrict__ colsum,
                             const float* __restrict__ Wpred, const float* __restrict__ bpred,
                             const float* __restrict__ Wcls, const float* __restrict__ bcls,
                             float* __restrict__ out) {
    __shared__ float cm[HH * (LL + 1)];
    __shared__ float gsh[HH];
    int tid = threadIdx.x;  // 128 threads
    for (int t = tid; t < HH * (LL + 1); t += 128) cm[t] = colsum[t] * (1.0f / (float)NN);
    __syncthreads();
    float g = bpred[tid];
    for (int k = 0; k < HH * (LL + 1); k++) g += cm[k] * Wpred[(size_t)k * HH + tid];
    gsh[tid] = g;
    __syncthreads();
    if (tid == 0) {
        float l0 = bcls[0], l1 = bcls[1];
        for (int j = 0; j < HH; j++) {
            l0 += gsh[j] * Wcls[j * 2 + 0];
            l1 += gsh[j] * Wcls[j * 2 + 1];
        }
        float m = fmaxf(l0, l1);
        float e0 = expf(l0 - m), e1 = expf(l1 - m);
        float inv = 1.0f / (e0 + e1);
        out[0] = e0 * inv;
        out[1] = e1 * inv;
    }
}

// ---------------- launch ----------------
extern "C" void kernel_launch(void* const* d_in, const int* in_sizes, int n_in,
                              void* d_out, int out_size) {
    const float* node_feat = (const float*)d_in[0];
    const float* degree    = (const float*)d_in[3];
    const float* Wn        = (const float*)d_in[4];
    const float* bn        = (const float*)d_in[5];
    const float* Wgcn      = (const float*)d_in[8];
    const float* bgcn      = (const float*)d_in[9];
    const float* Wpred     = (const float*)d_in[10];
    const float* bpred     = (const float*)d_in[11];
    const float* Wcls      = (const float*)d_in[12];
    const float* bcls      = (const float*)d_in[13];
    const int*   src       = (const int*)d_in[14];
    const int*   dst       = (const int*)d_in[15];
    float* out = (float*)d_out;

    float *p_h0, *p_cur, *p_hs, *p_agg, *p_cs;
    cudaGetSymbolAddress((void**)&p_h0,  g_h0);
    cudaGetSymbolAddress((void**)&p_cur, g_cur);
    cudaGetSymbolAddress((void**)&p_hs,  g_hs);
    cudaGetSymbolAddress((void**)&p_agg, g_agg);
    cudaGetSymbolAddress((void**)&p_cs,  g_colsum);

    const int n4 = NN * HH / 4;                 // 1,600,000
    const int zb = (n4 + 255) / 256;
    const int gemm_blocks = (NN + 127) / 128;   // 391
    const int scat_blocks = (EE * 32 + 255) / 256;  // 100000

    // 1) zero g_cur (fusion accumulator) and colsums
    zero_kernel<<<zb, 256>>>(p_cur, n4, p_cs);

    // 2) h0 = node_feat @ Wn + bn ; colsum[0:128]
    gemm_kernel<NF, false><<<gemm_blocks, 256>>>(node_feat, Wn, bn, p_h0, p_cs, 0);

    // 3) fusion: cur[dst] += h0[src]
    scatter_kernel<<<scat_blocks, 256>>>(p_h0, p_cur, src, dst);

    // 4) 3 GCN layers
    for (int l = 0; l < LL; l++) {
        prep_kernel<<<zb, 256>>>(p_cur, degree, p_hs, p_agg);
        scatter_kernel<<<scat_blocks, 256>>>(p_hs, p_agg, src, dst);
        gemm_kernel<HH, true><<<gemm_blocks, 256>>>(p_agg, Wgcn, bgcn, p_cur, p_cs,
                                                    (l + 1) * HH);
    }

    // 5) readout
    final_kernel<<<1, 128>>>(p_cs, Wpred, bpred, Wcls, bcls, out);
}

// round 4
// speedup vs baseline: 1.4170x; 1.4170x over previous
#include <cuda_runtime.h>
#include <cstddef>

#define NN 50000
#define EE 800000
#define NF 256
#define HH 128
#define LL 3
#define NEG_SLOPE 0.01f

// ---------------- scratch (no allocations allowed) ----------------
__device__ float g_h0 [(size_t)NN * HH];   // projection output
__device__ float g_cur[(size_t)NN * HH];   // current hidden h
__device__ float g_agg[(size_t)NN * HH];   // aggregation buffer (seeded with h)
__device__ float g_invdeg[NN];
__device__ float g_colsum[HH * (LL + 1)];  // column sums of the stack

// ---------------- helpers ----------------
__device__ __forceinline__ unsigned f2tf32(float x) {
    unsigned u;
    asm("cvt.rna.tf32.f32 %0, %1;" : "=r"(u) : "f"(x));
    return u;
}

__device__ __forceinline__ void mma_tf32(float* d, const unsigned* a, const unsigned* b) {
    asm volatile(
        "mma.sync.aligned.m16n8k8.row.col.f32.tf32.tf32.f32 "
        "{%0,%1,%2,%3}, {%4,%5,%6,%7}, {%8,%9}, {%0,%1,%2,%3};\n"
        : "+f"(d[0]), "+f"(d[1]), "+f"(d[2]), "+f"(d[3])
        : "r"(a[0]), "r"(a[1]), "r"(a[2]), "r"(a[3]), "r"(b[0]), "r"(b[1]));
}

// ---------------- init: zero cur + colsum, compute invdeg ----------------
__global__ void init_kernel(float* __restrict__ cur, float* __restrict__ cs,
                            const float* __restrict__ degree, float* __restrict__ invdeg) {
    int i = blockIdx.x * blockDim.x + threadIdx.x;
    const int n4 = NN * HH / 4;
    if (i < n4) reinterpret_cast<float4*>(cur)[i] = make_float4(0.f, 0.f, 0.f, 0.f);
    if (i < HH * (LL + 1)) cs[i] = 0.f;
    if (i < NN) invdeg[i] = 1.0f / degree[i];
}

// ---------------- copy (float4) ----------------
__global__ void copy_kernel(const float* __restrict__ in, float* __restrict__ out) {
    int i = blockIdx.x * blockDim.x + threadIdx.x;
    const int n4 = NN * HH / 4;
    if (i < n4) reinterpret_cast<float4*>(out)[i] = reinterpret_cast<const float4*>(in)[i];
}

// ---------------- tf32 tensor-core GEMM ----------------
// C[M,128] = leaky?(A[M,K] @ W[K,128] + bias); optional dual store to C2;
// accumulates per-column sums into colsum[cs_off..].
template <int K, bool LEAKY, bool DUAL>
__global__ __launch_bounds__(256, 2)
void gemm_tc(const float* __restrict__ A, const float* __restrict__ W,
             const float* __restrict__ bias, float* __restrict__ C,
             float* __restrict__ C2, float* __restrict__ colsum, int cs_off) {
    __shared__ unsigned As[128][36];   // [row][k], padded
    __shared__ unsigned Ws[32][132];   // [k][n], padded
    __shared__ float colsm[HH];

    const int tid = threadIdx.x;
    const int warp = tid >> 5, lane = tid & 31;
    const int wm = warp & 3, wn = warp >> 2;      // warp tile: 32 rows x 64 cols
    const int g = lane >> 2, t = lane & 3;
    const int row0 = blockIdx.x * 128;

    float acc[2][8][4];
#pragma unroll
    for (int mt = 0; mt < 2; mt++)
#pragma unroll
        for (int nt = 0; nt < 8; nt++)
#pragma unroll
            for (int r = 0; r < 4; r++) acc[mt][nt][r] = 0.f;

    if (tid < HH) colsm[tid] = 0.f;

    for (int k0 = 0; k0 < K; k0 += 32) {
        // A tile: 128 rows x 32 k (1024 float4, 4 per thread)
#pragma unroll
        for (int i = 0; i < 4; i++) {
            int idx = tid + i * 256;
            int r = idx >> 3, q = idx & 7;
            float4 v = make_float4(0.f, 0.f, 0.f, 0.f);
            if (row0 + r < NN)
                v = *reinterpret_cast<const float4*>(A + (size_t)(row0 + r) * K + k0 + q * 4);
            unsigned* p = &As[r][q * 4];
            p[0] = f2tf32(v.x); p[1] = f2tf32(v.y); p[2] = f2tf32(v.z); p[3] = f2tf32(v.w);
        }
        // W tile: 32 k x 128 n
#pragma unroll
        for (int i = 0; i < 4; i++) {
            int idx = tid + i * 256;
            int kk = idx >> 5, n4 = idx & 31;
            float4 w = *reinterpret_cast<const float4*>(W + (size_t)(k0 + kk) * HH + n4 * 4);
            unsigned* p = &Ws[kk][n4 * 4];
            p[0] = f2tf32(w.x); p[1] = f2tf32(w.y); p[2] = f2tf32(w.z); p[3] = f2tf32(w.w);
        }
        __syncthreads();

#pragma unroll
        for (int k8 = 0; k8 < 4; k8++) {
            const int kk = k8 * 8;
            unsigned a[2][4], b[8][2];
#pragma unroll
            for (int mt = 0; mt < 2; mt++) {
                int r = wm * 32 + mt * 16;
                a[mt][0] = As[r + g][kk + t];
                a[mt][1] = As[r + g + 8][kk + t];
                a[mt][2] = As[r + g][kk + t + 4];
                a[mt][3] = As[r + g + 8][kk + t + 4];
            }
#pragma unroll
            for (int nt = 0; nt < 8; nt++) {
                int n = wn * 64 + nt * 8;
                b[nt][0] = Ws[kk + t][n + g];
                b[nt][1] = Ws[kk + t + 4][n + g];
            }
#pragma unroll
            for (int mt = 0; mt < 2; mt++)
#pragma unroll
                for (int nt = 0; nt < 8; nt++)
                    mma_tf32(acc[mt][nt], a[mt], b[nt]);
        }
        __syncthreads();
    }

    // ---------------- epilogue ----------------
    float csum[8][2];
#pragma unroll
    for (int nt = 0; nt < 8; nt++) { csum[nt][0] = 0.f; csum[nt][1] = 0.f; }

#pragma unroll
    for (int mt = 0; mt < 2; mt++) {
        int r1 = row0 + wm * 32 + mt * 16 + g;
        int r2 = r1 + 8;
#pragma unroll
        for (int nt = 0; nt < 8; nt++) {
            int col = wn * 64 + nt * 8 + 2 * t;
            float b0 = __ldg(bias + col), b1 = __ldg(bias + col + 1);
            float x0 = acc[mt][nt][0] + b0, x1 = acc[mt][nt][1] + b1;
            float x2 = acc[mt][nt][2] + b0, x3 = acc[mt][nt][3] + b1;
            if (LEAKY) {
                x0 = (x0 >= 0.f) ? x0 : NEG_SLOPE * x0;
                x1 = (x1 >= 0.f) ? x1 : NEG_SLOPE * x1;
                x2 = (x2 >= 0.f) ? x2 : NEG_SLOPE * x2;
                x3 = (x3 >= 0.f) ? x3 : NEG_SLOPE * x3;
            }
            if (r1 < NN) {
                *reinterpret_cast<float2*>(C + (size_t)r1 * HH + col) = make_float2(x0, x1);
                if (DUAL)
                    *reinterpret_cast<float2*>(C2 + (size_t)r1 * HH + col) = make_float2(x0, x1);
                csum[nt][0] += x0; csum[nt][1] += x1;
            }
            if (r2 < NN) {
                *reinterpret_cast<float2*>(C + (size_t)r2 * HH + col) = make_float2(x2, x3);
                if (DUAL)
                    *reinterpret_cast<float2*>(C2 + (size_t)r2 * HH + col) = make_float2(x2, x3);
                csum[nt][0] += x2; csum[nt][1] += x3;
            }
        }
    }

    __syncthreads();  // colsm zero visible
#pragma unroll
    for (int nt = 0; nt < 8; nt++) {
#pragma unroll
        for (int c = 0; c < 2; c++) {
            float s = csum[nt][c];
            s += __shfl_xor_sync(0xffffffffu, s, 4);
            s += __shfl_xor_sync(0xffffffffu, s, 8);
            s += __shfl_xor_sync(0xffffffffu, s, 16);
            if (g == 0) atomicAdd(&colsm[wn * 64 + nt * 8 + 2 * t + c], s);
        }
    }
    __syncthreads();
    if (tid < HH) atomicAdd(&colsum[cs_off + tid], colsm[tid]);
}

// ---------------- edge scatter: out[dst] += msg[src] (* invdeg[src]) ----------------
template <bool SCALED>
__global__ __launch_bounds__(256)
void scatter_kernel(const float* __restrict__ msg, const float* __restrict__ invdeg,
                    float* __restrict__ out,
                    const int* __restrict__ src, const int* __restrict__ dst) {
    int e = (blockIdx.x * blockDim.x + threadIdx.x) >> 5;
    int lane = threadIdx.x & 31;
    if (e >= EE) return;
    int s = __ldg(src + e);
    int d = __ldg(dst + e);
    float4 v = *reinterpret_cast<const float4*>(msg + (size_t)s * HH + lane * 4);
    if (SCALED) {
        float iv = __ldg(invdeg + s);
        v.x *= iv; v.y *= iv; v.z *= iv; v.w *= iv;
    }
    atomicAdd(reinterpret_cast<float4*>(out + (size_t)d * HH + lane * 4), v);
}

// ---------------- final: column means -> Wpred -> Wcls -> softmax ----------------
__global__ void final_kernel(const float* __restrict__ colsum,
                             const float* __restrict__ Wpred, const float* __restrict__ bpred,
                             const float* __restrict__ Wcls, const float* __restrict__ bcls,
                             float* __restrict__ out) {
    __shared__ float cm[HH * (LL + 1)];
    __shared__ float gsh[HH];
    int tid = threadIdx.x;  // 128 threads
    for (int t = tid; t < HH * (LL + 1); t += 128) cm[t] = colsum[t] * (1.0f / (float)NN);
    __syncthreads();
    float g = bpred[tid];
    for (int k = 0; k < HH * (LL + 1); k++) g += cm[k] * Wpred[(size_t)k * HH + tid];
    gsh[tid] = g;
    __syncthreads();
    if (tid == 0) {
        float l0 = bcls[0], l1 = bcls[1];
        for (int j = 0; j < HH; j++) {
            l0 += gsh[j] * Wcls[j * 2 + 0];
            l1 += gsh[j] * Wcls[j * 2 + 1];
        }
        float m = fmaxf(l0, l1);
        float e0 = expf(l0 - m), e1 = expf(l1 - m);
        float inv = 1.0f / (e0 + e1);
        out[0] = e0 * inv;
        out[1] = e1 * inv;
    }
}

// ---------------- launch ----------------
extern "C" void kernel_launch(void* const* d_in, const int* in_sizes, int n_in,
                              void* d_out, int out_size) {
    const float* node_feat = (const float*)d_in[0];
    const float* degree    = (const float*)d_in[3];
    const float* Wn        = (const float*)d_in[4];
    const float* bn        = (const float*)d_in[5];
    const float* Wgcn      = (const float*)d_in[8];
    const float* bgcn      = (const float*)d_in[9];
    const float* Wpred     = (const float*)d_in[10];
    const float* bpred     = (const float*)d_in[11];
    const float* Wcls      = (const float*)d_in[12];
    const float* bcls      = (const float*)d_in[13];
    const int*   src       = (const int*)d_in[14];
    const int*   dst       = (const int*)d_in[15];
    float* out = (float*)d_out;

    float *p_h0, *p_cur, *p_agg, *p_inv, *p_cs;
    cudaGetSymbolAddress((void**)&p_h0,  g_h0);
    cudaGetSymbolAddress((void**)&p_cur, g_cur);
    cudaGetSymbolAddress((void**)&p_agg, g_agg);
    cudaGetSymbolAddress((void**)&p_inv, g_invdeg);
    cudaGetSymbolAddress((void**)&p_cs,  g_colsum);

    const int n4 = NN * HH / 4;
    const int zb = (n4 + 255) / 256;
    const int gemm_blocks = (NN + 127) / 128;       // 391
    const int scat_blocks = (EE * 32 + 255) / 256;  // 100000

    // 1) zero cur + colsum, compute invdeg
    init_kernel<<<zb, 256>>>(p_cur, p_cs, degree, p_inv);

    // 2) projection: h0 = node_feat @ Wn + bn ; colsum[0:128]
    gemm_tc<NF, false, false><<<gemm_blocks, 256>>>(node_feat, Wn, bn, p_h0, nullptr, p_cs, 0);

    // 3) fusion: cur[dst] += h0[src]
    scatter_kernel<false><<<scat_blocks, 256>>>(p_h0, nullptr, p_cur, src, dst);

    // 4) seed agg = cur
    copy_kernel<<<zb, 256>>>(p_cur, p_agg);

    // 5) 3 GCN layers
    for (int l = 0; l < LL; l++) {
        // agg[dst] += cur[src] * invdeg[src]
        scatter_kernel<true><<<scat_blocks, 256>>>(p_cur, p_inv, p_agg, src, dst);
        // cur = leaky(agg @ Wgcn + bgcn); (dual-store agg = cur for next layer)
        if (l < LL - 1)
            gemm_tc<HH, true, true><<<gemm_blocks, 256>>>(p_agg, Wgcn, bgcn, p_cur, p_agg,
                                                          p_cs, (l + 1) * HH);
        else
            gemm_tc<HH, true, false><<<gemm_blocks, 256>>>(p_agg, Wgcn, bgcn, p_cur, nullptr,
                                                           p_cs, (l + 1) * HH);
    }

    // 6) readout
    final_kernel<<<1, 128>>>(p_cs, Wpred, bpred, Wcls, bcls, out);
}

// round 5
// speedup vs baseline: 2.2562x; 1.5923x over previous
#include <cuda_runtime.h>
#include <cstddef>

#define NN 50000
#define EE 800000
#define NF 256
#define HH 128
#define LL 3
#define NEG_SLOPE 0.01f

// ---------------- scratch (no allocations allowed) ----------------
__device__ float g_h0 [(size_t)NN * HH];   // projection output
__device__ float g_cur[(size_t)NN * HH];   // current hidden h
__device__ float g_agg[(size_t)NN * HH];   // aggregation buffer
__device__ float g_invdeg[NN];
__device__ float g_colsum[HH * (LL + 1)];
__device__ int   g_cnt[NN];
__device__ int   g_pos[NN];
__device__ int   g_rowptr[NN + 1];
__device__ int   g_col[EE];                // src node per dst-sorted edge

// ---------------- helpers ----------------
__device__ __forceinline__ unsigned f2tf32(float x) {
    unsigned u;
    asm("cvt.rna.tf32.f32 %0, %1;" : "=r"(u) : "f"(x));
    return u;
}

__device__ __forceinline__ void mma_tf32(float* d, const unsigned* a, const unsigned* b) {
    asm volatile(
        "mma.sync.aligned.m16n8k8.row.col.f32.tf32.tf32.f32 "
        "{%0,%1,%2,%3}, {%4,%5,%6,%7}, {%8,%9}, {%0,%1,%2,%3};\n"
        : "+f"(d[0]), "+f"(d[1]), "+f"(d[2]), "+f"(d[3])
        : "r"(a[0]), "r"(a[1]), "r"(a[2]), "r"(a[3]), "r"(b[0]), "r"(b[1]));
}

// ---------------- init: zero counters + colsum, compute invdeg ----------------
__global__ void init_kernel(const float* __restrict__ degree, float* __restrict__ invdeg,
                            int* __restrict__ cnt, int* __restrict__ pos,
                            float* __restrict__ cs) {
    int i = blockIdx.x * blockDim.x + threadIdx.x;
    if (i < NN) {
        invdeg[i] = 1.0f / degree[i];
        cnt[i] = 0;
        pos[i] = 0;
    }
    if (i < HH * (LL + 1)) cs[i] = 0.f;
}

// ---------------- CSR build ----------------
__global__ void hist_kernel(const int* __restrict__ dst, int* __restrict__ cnt) {
    int e = blockIdx.x * blockDim.x + threadIdx.x;
    if (e < EE) atomicAdd(&cnt[dst[e]], 1);
}

__global__ void scan_kernel(const int* __restrict__ cnt, int* __restrict__ rowptr) {
    __shared__ int wsum[32];
    __shared__ int carry;
    int tid = threadIdx.x, lane = tid & 31, wid = tid >> 5;
    if (tid == 0) carry = 0;
    __syncthreads();
    for (int base = 0; base < NN; base += 1024) {
        int i = base + tid;
        int v = (i < NN) ? cnt[i] : 0;
        int x = v;
#pragma unroll
        for (int off = 1; off < 32; off <<= 1) {
            int y = __shfl_up_sync(0xffffffffu, x, off);
            if (lane >= off) x += y;
        }
        if (lane == 31) wsum[wid] = x;
        __syncthreads();
        if (wid == 0) {
            int s = wsum[lane];
#pragma unroll
            for (int off = 1; off < 32; off <<= 1) {
                int y = __shfl_up_sync(0xffffffffu, s, off);
                if (lane >= off) s += y;
            }
            wsum[lane] = s;
        }
        __syncthreads();
        int woff = (wid == 0) ? 0 : wsum[wid - 1];
        if (i < NN) rowptr[i] = carry + woff + x - v;   // exclusive
        int total = wsum[31];
        __syncthreads();
        if (tid == 0) carry += total;
        __syncthreads();
    }
    if (threadIdx.x == 0) rowptr[NN] = carry;
}

__global__ void fill_kernel(const int* __restrict__ src, const int* __restrict__ dst,
                            const int* __restrict__ rowptr, int* __restrict__ pos,
                            int* __restrict__ col) {
    int e = blockIdx.x * blockDim.x + threadIdx.x;
    if (e >= EE) return;
    int d = dst[e];
    int p = atomicAdd(&pos[d], 1);
    col[rowptr[d] + p] = src[e];
}

// ---------------- gather: out[v] = (base[v]?) + sum_{u->v} msg[u] (*invdeg[u]) ----------
template <bool SCALED, bool ADDBASE>
__global__ __launch_bounds__(256)
void gather_kernel(const float* __restrict__ msg, const float* __restrict__ invdeg,
                   const float* __restrict__ base, float* __restrict__ out,
                   const int* __restrict__ rowptr, const int* __restrict__ col) {
    int node = (blockIdx.x * blockDim.x + threadIdx.x) >> 5;
    int lane = threadIdx.x & 31;
    if (node >= NN) return;
    int s0 = __ldg(rowptr + node), s1 = __ldg(rowptr + node + 1);
    float4 acc;
    if (ADDBASE)
        acc = *reinterpret_cast<const float4*>(base + (size_t)node * HH + lane * 4);
    else
        acc = make_float4(0.f, 0.f, 0.f, 0.f);

    int e = s0;
    for (; e + 1 < s1; e += 2) {
        int u0 = __ldg(col + e), u1 = __ldg(col + e + 1);
        float4 v0 = *reinterpret_cast<const float4*>(msg + (size_t)u0 * HH + lane * 4);
        float4 v1 = *reinterpret_cast<const float4*>(msg + (size_t)u1 * HH + lane * 4);
        float i0 = SCALED ? __ldg(invdeg + u0) : 1.0f;
        float i1 = SCALED ? __ldg(invdeg + u1) : 1.0f;
        acc.x += v0.x * i0; acc.y += v0.y * i0; acc.z += v0.z * i0; acc.w += v0.w * i0;
        acc.x += v1.x * i1; acc.y += v1.y * i1; acc.z += v1.z * i1; acc.w += v1.w * i1;
    }
    if (e < s1) {
        int u0 = __ldg(col + e);
        float4 v0 = *reinterpret_cast<const float4*>(msg + (size_t)u0 * HH + lane * 4);
        float i0 = SCALED ? __ldg(invdeg + u0) : 1.0f;
        acc.x += v0.x * i0; acc.y += v0.y * i0; acc.z += v0.z * i0; acc.w += v0.w * i0;
    }
    *reinterpret_cast<float4*>(out + (size_t)node * HH + lane * 4) = acc;
}

// ---------------- tf32 tensor-core GEMM ----------------
// C[M,128] = leaky?(A[M,K] @ W[K,128] + bias); accumulates colsum[cs_off..].
template <int K, bool LEAKY>
__global__ __launch_bounds__(256, 2)
void gemm_tc(const float* __restrict__ A, const float* __restrict__ W,
             const float* __restrict__ bias, float* __restrict__ C,
             float* __restrict__ colsum, int cs_off) {
    __shared__ unsigned As[128][36];
    __shared__ unsigned Ws[32][132];
    __shared__ float colsm[HH];

    const int tid = threadIdx.x;
    const int warp = tid >> 5, lane = tid & 31;
    const int wm = warp & 3, wn = warp >> 2;
    const int g = lane >> 2, t = lane & 3;
    const int row0 = blockIdx.x * 128;

    float acc[2][8][4];
#pragma unroll
    for (int mt = 0; mt < 2; mt++)
#pragma unroll
        for (int nt = 0; nt < 8; nt++)
#pragma unroll
            for (int r = 0; r < 4; r++) acc[mt][nt][r] = 0.f;

    if (tid < HH) colsm[tid] = 0.f;

    for (int k0 = 0; k0 < K; k0 += 32) {
#pragma unroll
        for (int i = 0; i < 4; i++) {
            int idx = tid + i * 256;
            int r = idx >> 3, q = idx & 7;
            float4 v = make_float4(0.f, 0.f, 0.f, 0.f);
            if (row0 + r < NN)
                v = *reinterpret_cast<const float4*>(A + (size_t)(row0 + r) * K + k0 + q * 4);
            unsigned* p = &As[r][q * 4];
            p[0] = f2tf32(v.x); p[1] = f2tf32(v.y); p[2] = f2tf32(v.z); p[3] = f2tf32(v.w);
        }
#pragma unroll
        for (int i = 0; i < 4; i++) {
            int idx = tid + i * 256;
            int kk = idx >> 5, n4 = idx & 31;
            float4 w = *reinterpret_cast<const float4*>(W + (size_t)(k0 + kk) * HH + n4 * 4);
            unsigned* p = &Ws[kk][n4 * 4];
            p[0] = f2tf32(w.x); p[1] = f2tf32(w.y); p[2] = f2tf32(w.z); p[3] = f2tf32(w.w);
        }
        __syncthreads();

#pragma unroll
        for (int k8 = 0; k8 < 4; k8++) {
            const int kk = k8 * 8;
            unsigned a[2][4], b[8][2];
#pragma unroll
            for (int mt = 0; mt < 2; mt++) {
                int r = wm * 32 + mt * 16;
                a[mt][0] = As[r + g][kk + t];
                a[mt][1] = As[r + g + 8][kk + t];
                a[mt][2] = As[r + g][kk + t + 4];
                a[mt][3] = As[r + g + 8][kk + t + 4];
            }
#pragma unroll
            for (int nt = 0; nt < 8; nt++) {
                int n = wn * 64 + nt * 8;
                b[nt][0] = Ws[kk + t][n + g];
                b[nt][1] = Ws[kk + t + 4][n + g];
            }
#pragma unroll
            for (int mt = 0; mt < 2; mt++)
#pragma unroll
                for (int nt = 0; nt < 8; nt++)
                    mma_tf32(acc[mt][nt], a[mt], b[nt]);
        }
        __syncthreads();
    }

    float csum[8][2];
#pragma unroll
    for (int nt = 0; nt < 8; nt++) { csum[nt][0] = 0.f; csum[nt][1] = 0.f; }

#pragma unroll
    for (int mt = 0; mt < 2; mt++) {
        int r1 = row0 + wm * 32 + mt * 16 + g;
        int r2 = r1 + 8;
#pragma unroll
        for (int nt = 0; nt < 8; nt++) {
            int col = wn * 64 + nt * 8 + 2 * t;
            float b0 = __ldg(bias + col), b1 = __ldg(bias + col + 1);
            float x0 = acc[mt][nt][0] + b0, x1 = acc[mt][nt][1] + b1;
            float x2 = acc[mt][nt][2] + b0, x3 = acc[mt][nt][3] + b1;
            if (LEAKY) {
                x0 = (x0 >= 0.f) ? x0 : NEG_SLOPE * x0;
                x1 = (x1 >= 0.f) ? x1 : NEG_SLOPE * x1;
                x2 = (x2 >= 0.f) ? x2 : NEG_SLOPE * x2;
                x3 = (x3 >= 0.f) ? x3 : NEG_SLOPE * x3;
            }
            if (r1 < NN) {
                *reinterpret_cast<float2*>(C + (size_t)r1 * HH + col) = make_float2(x0, x1);
                csum[nt][0] += x0; csum[nt][1] += x1;
            }
            if (r2 < NN) {
                *reinterpret_cast<float2*>(C + (size_t)r2 * HH + col) = make_float2(x2, x3);
                csum[nt][0] += x2; csum[nt][1] += x3;
            }
        }
    }

    __syncthreads();
#pragma unroll
    for (int nt = 0; nt < 8; nt++) {
#pragma unroll
        for (int c = 0; c < 2; c++) {
            float s = csum[nt][c];
            s += __shfl_xor_sync(0xffffffffu, s, 4);
            s += __shfl_xor_sync(0xffffffffu, s, 8);
            s += __shfl_xor_sync(0xffffffffu, s, 16);
            if (g == 0) atomicAdd(&colsm[wn * 64 + nt * 8 + 2 * t + c], s);
        }
    }
    __syncthreads();
    if (tid < HH) atomicAdd(&colsum[cs_off + tid], colsm[tid]);
}

// ---------------- final: column means -> Wpred -> Wcls -> softmax ----------------
__global__ void final_kernel(const float* __restrict__ colsum,
                             const float* __restrict__ Wpred, const float* __restrict__ bpred,
                             const float* __restrict__ Wcls, const float* __restrict__ bcls,
                             float* __restrict__ out) {
    __shared__ float cm[HH * (LL + 1)];
    __shared__ float gsh[HH];
    int tid = threadIdx.x;  // 128 threads
    for (int t = tid; t < HH * (LL + 1); t += 128) cm[t] = colsum[t] * (1.0f / (float)NN);
    __syncthreads();
    float g = bpred[tid];
    for (int k = 0; k < HH * (LL + 1); k++) g += cm[k] * Wpred[(size_t)k * HH + tid];
    gsh[tid] = g;
    __syncthreads();
    if (tid == 0) {
        float l0 = bcls[0], l1 = bcls[1];
        for (int j = 0; j < HH; j++) {
            l0 += gsh[j] * Wcls[j * 2 + 0];
            l1 += gsh[j] * Wcls[j * 2 + 1];
        }
        float m = fmaxf(l0, l1);
        float e0 = expf(l0 - m), e1 = expf(l1 - m);
        float inv = 1.0f / (e0 + e1);
        out[0] = e0 * inv;
        out[1] = e1 * inv;
    }
}

// ---------------- launch ----------------
extern "C" void kernel_launch(void* const* d_in, const int* in_sizes, int n_in,
                              void* d_out, int out_size) {
    const float* node_feat = (const float*)d_in[0];
    const float* degree    = (const float*)d_in[3];
    const float* Wn        = (const float*)d_in[4];
    const float* bn        = (const float*)d_in[5];
    const float* Wgcn      = (const float*)d_in[8];
    const float* bgcn      = (const float*)d_in[9];
    const float* Wpred     = (const float*)d_in[10];
    const float* bpred     = (const float*)d_in[11];
    const float* Wcls      = (const float*)d_in[12];
    const float* bcls      = (const float*)d_in[13];
    const int*   src       = (const int*)d_in[14];
    const int*   dst       = (const int*)d_in[15];
    float* out = (float*)d_out;

    float *p_h0, *p_cur, *p_agg, *p_inv, *p_cs;
    int *p_cnt, *p_pos, *p_rp, *p_col;
    cudaGetSymbolAddress((void**)&p_h0,  g_h0);
    cudaGetSymbolAddress((void**)&p_cur, g_cur);
    cudaGetSymbolAddress((void**)&p_agg, g_agg);
    cudaGetSymbolAddress((void**)&p_inv, g_invdeg);
    cudaGetSymbolAddress((void**)&p_cs,  g_colsum);
    cudaGetSymbolAddress((void**)&p_cnt, g_cnt);
    cudaGetSymbolAddress((void**)&p_pos, g_pos);
    cudaGetSymbolAddress((void**)&p_rp,  g_rowptr);
    cudaGetSymbolAddress((void**)&p_col, g_col);

    const int gemm_blocks = (NN + 127) / 128;        // 391
    const int edge_blocks = (EE + 255) / 256;        // 3125
    const int node_blocks = (NN + 255) / 256;        // 196
    const int gath_blocks = (NN * 32 + 255) / 256;   // 6250

    // 1) init counters / invdeg / colsum
    init_kernel<<<node_blocks, 256>>>(degree, p_inv, p_cnt, p_pos, p_cs);

    // 2) CSR build (dst-major)
    hist_kernel<<<edge_blocks, 256>>>(dst, p_cnt);
    scan_kernel<<<1, 1024>>>(p_cnt, p_rp);
    fill_kernel<<<edge_blocks, 256>>>(src, dst, p_rp, p_pos, p_col);

    // 3) projection: h0 = node_feat @ Wn + bn ; colsum[0:128]
    gemm_tc<NF, false><<<gemm_blocks, 256>>>(node_feat, Wn, bn, p_h0, p_cs, 0);

    // 4) fusion: cur[v] = sum_{u->v} h0[u]
    gather_kernel<false, false><<<gath_blocks, 256>>>(p_h0, nullptr, nullptr, p_cur,
                                                      p_rp, p_col);

    // 5) 3 GCN layers
    for (int l = 0; l < LL; l++) {
        // agg[v] = cur[v] + sum_{u->v} cur[u]*invdeg[u]
        gather_kernel<true, true><<<gath_blocks, 256>>>(p_cur, p_inv, p_cur, p_agg,
                                                        p_rp, p_col);
        // cur = leaky(agg @ Wgcn + bgcn)
        gemm_tc<HH, true><<<gemm_blocks, 256>>>(p_agg, Wgcn, bgcn, p_cur, p_cs,
                                                (l + 1) * HH);
    }

    // 6) readout
    final_kernel<<<1, 128>>>(p_cs, Wpred, bpred, Wcls, bcls, out);
}

// round 6
// speedup vs baseline: 2.4707x; 1.0951x over previous
#include <cuda_runtime.h>
#include <cuda_bf16.h>
#include <cstddef>

#define NN 50000
#define EE 800000
#define NF 256
#define HH 128
#define LL 3
#define NEG_SLOPE 0.01f

// ---------------- scratch (no allocations allowed) ----------------
__device__ float         g_cur[(size_t)NN * HH];   // current hidden h (fp32)
__device__ float         g_agg[(size_t)NN * HH];   // aggregation buffer (fp32)
__device__ __nv_bfloat16 g_h0b[(size_t)NN * HH];   // projection output (bf16)
__device__ __nv_bfloat16 g_msgb[(size_t)NN * HH];  // h*invdeg messages (bf16)
__device__ float g_invdeg[NN];
__device__ float g_colsum[HH * (LL + 1)];
__device__ int   g_cnt[NN];
__device__ int   g_pos[NN];
__device__ int   g_rowptr[NN + 1];
__device__ int   g_col[EE];                // src node per dst-sorted edge

// ---------------- helpers ----------------
__device__ __forceinline__ unsigned f2tf32(float x) {
    unsigned u;
    asm("cvt.rna.tf32.f32 %0, %1;" : "=r"(u) : "f"(x));
    return u;
}

__device__ __forceinline__ void mma_tf32(float* d, const unsigned* a, const unsigned* b) {
    asm volatile(
        "mma.sync.aligned.m16n8k8.row.col.f32.tf32.tf32.f32 "
        "{%0,%1,%2,%3}, {%4,%5,%6,%7}, {%8,%9}, {%0,%1,%2,%3};\n"
        : "+f"(d[0]), "+f"(d[1]), "+f"(d[2]), "+f"(d[3])
        : "r"(a[0]), "r"(a[1]), "r"(a[2]), "r"(a[3]), "r"(b[0]), "r"(b[1]));
}

__device__ __forceinline__ void acc_bf16row(float4& acc, const __nv_bfloat16* p) {
    uint2 r = *reinterpret_cast<const uint2*>(p);
    __nv_bfloat162 b0 = *reinterpret_cast<const __nv_bfloat162*>(&r.x);
    __nv_bfloat162 b1 = *reinterpret_cast<const __nv_bfloat162*>(&r.y);
    float2 f0 = __bfloat1622float2(b0);
    float2 f1 = __bfloat1622float2(b1);
    acc.x += f0.x; acc.y += f0.y; acc.z += f1.x; acc.w += f1.y;
}

// ---------------- init: counters + colsum + invdeg ----------------
__global__ void init_kernel(const float* __restrict__ degree, float* __restrict__ invdeg,
                            int* __restrict__ cnt, int* __restrict__ pos,
                            float* __restrict__ cs) {
    int i = blockIdx.x * blockDim.x + threadIdx.x;
    if (i < NN) {
        invdeg[i] = 1.0f / degree[i];
        cnt[i] = 0;
        pos[i] = 0;
    }
    if (i < HH * (LL + 1)) cs[i] = 0.f;
}

// ---------------- CSR build ----------------
__global__ void hist_kernel(const int* __restrict__ dst, int* __restrict__ cnt) {
    int e = blockIdx.x * blockDim.x + threadIdx.x;
    if (e < EE) atomicAdd(&cnt[dst[e]], 1);
}

__global__ void scan_kernel(const int* __restrict__ cnt, int* __restrict__ rowptr) {
    __shared__ int wsum[32];
    __shared__ int carry;
    int tid = threadIdx.x, lane = tid & 31, wid = tid >> 5;
    if (tid == 0) carry = 0;
    __syncthreads();
    for (int base = 0; base < NN; base += 1024) {
        int i = base + tid;
        int v = (i < NN) ? cnt[i] : 0;
        int x = v;
#pragma unroll
        for (int off = 1; off < 32; off <<= 1) {
            int y = __shfl_up_sync(0xffffffffu, x, off);
            if (lane >= off) x += y;
        }
        if (lane == 31) wsum[wid] = x;
        __syncthreads();
        if (wid == 0) {
            int s = wsum[lane];
#pragma unroll
            for (int off = 1; off < 32; off <<= 1) {
                int y = __shfl_up_sync(0xffffffffu, s, off);
                if (lane >= off) s += y;
            }
            wsum[lane] = s;
        }
        __syncthreads();
        int woff = (wid == 0) ? 0 : wsum[wid - 1];
        if (i < NN) rowptr[i] = carry + woff + x - v;   // exclusive
        int total = wsum[31];
        __syncthreads();
        if (tid == 0) carry += total;
        __syncthreads();
    }
    if (threadIdx.x == 0) rowptr[NN] = carry;
}

__global__ void fill_kernel(const int* __restrict__ src, const int* __restrict__ dst,
                            const int* __restrict__ rowptr, int* __restrict__ pos,
                            int* __restrict__ col) {
    int e = blockIdx.x * blockDim.x + threadIdx.x;
    if (e >= EE) return;
    int d = dst[e];
    int p = atomicAdd(&pos[d], 1);
    col[rowptr[d] + p] = src[e];
}

// ---------------- gather (bf16 messages): out[v] = (base[v]?) + sum msg[u] -------------
// OUTB16: additionally write outb[v] = out[v]*invdeg[v] as bf16.
template <bool ADDBASE, bool OUTB16>
__global__ __launch_bounds__(256)
void gather_kernel(const __nv_bfloat16* __restrict__ msg, const float* __restrict__ base,
                   float* __restrict__ out, __nv_bfloat16* __restrict__ outb,
                   const float* __restrict__ invdeg,
                   const int* __restrict__ rowptr, const int* __restrict__ col) {
    int node = (blockIdx.x * blockDim.x + threadIdx.x) >> 5;
    int lane = threadIdx.x & 31;
    if (node >= NN) return;
    int s0 = __ldg(rowptr + node), s1 = __ldg(rowptr + node + 1);

    float4 acc;
    if (ADDBASE)
        acc = *reinterpret_cast<const float4*>(base + (size_t)node * HH + lane * 4);
    else
        acc = make_float4(0.f, 0.f, 0.f, 0.f);

    const __nv_bfloat16* mbase = msg + lane * 4;
    int e = s0;
    for (; e + 3 < s1; e += 4) {
        int u0 = __ldg(col + e),     u1 = __ldg(col + e + 1);
        int u2 = __ldg(col + e + 2), u3 = __ldg(col + e + 3);
        acc_bf16row(acc, mbase + (size_t)u0 * HH);
        acc_bf16row(acc, mbase + (size_t)u1 * HH);
        acc_bf16row(acc, mbase + (size_t)u2 * HH);
        acc_bf16row(acc, mbase + (size_t)u3 * HH);
    }
    for (; e < s1; e++) {
        int u0 = __ldg(col + e);
        acc_bf16row(acc, mbase + (size_t)u0 * HH);
    }

    *reinterpret_cast<float4*>(out + (size_t)node * HH + lane * 4) = acc;
    if (OUTB16) {
        float iv = __ldg(invdeg + node);
        __nv_bfloat162 o0 = __floats2bfloat162_rn(acc.x * iv, acc.y * iv);
        __nv_bfloat162 o1 = __floats2bfloat162_rn(acc.z * iv, acc.w * iv);
        uint2 packed;
        packed.x = *reinterpret_cast<unsigned*>(&o0);
        packed.y = *reinterpret_cast<unsigned*>(&o1);
        *reinterpret_cast<uint2*>(outb + (size_t)node * HH + lane * 4) = packed;
    }
}

// ---------------- tf32 tensor-core GEMM ----------------
// OUTMODE: 0 = colsum only; 1 = bf16 unscaled to Cb; 2 = fp32 to C + bf16*invdeg to Cb.
template <int K, bool LEAKY, int OUTMODE>
__global__ __launch_bounds__(256, 2)
void gemm_tc(const float* __restrict__ A, const float* __restrict__ W,
             const float* __restrict__ bias, float* __restrict__ C,
             __nv_bfloat16* __restrict__ Cb, const float* __restrict__ invdeg,
             float* __restrict__ colsum, int cs_off) {
    __shared__ unsigned As[128][36];
    __shared__ unsigned Ws[32][132];
    __shared__ float colsm[HH];

    const int tid = threadIdx.x;
    const int warp = tid >> 5, lane = tid & 31;
    const int wm = warp & 3, wn = warp >> 2;
    const int g = lane >> 2, t = lane & 3;
    const int row0 = blockIdx.x * 128;

    float acc[2][8][4];
#pragma unroll
    for (int mt = 0; mt < 2; mt++)
#pragma unroll
        for (int nt = 0; nt < 8; nt++)
#pragma unroll
            for (int r = 0; r < 4; r++) acc[mt][nt][r] = 0.f;

    if (tid < HH) colsm[tid] = 0.f;

    for (int k0 = 0; k0 < K; k0 += 32) {
#pragma unroll
        for (int i = 0; i < 4; i++) {
            int idx = tid + i * 256;
            int r = idx >> 3, q = idx & 7;
            float4 v = make_float4(0.f, 0.f, 0.f, 0.f);
            if (row0 + r < NN)
                v = *reinterpret_cast<const float4*>(A + (size_t)(row0 + r) * K + k0 + q * 4);
            unsigned* p = &As[r][q * 4];
            p[0] = f2tf32(v.x); p[1] = f2tf32(v.y); p[2] = f2tf32(v.z); p[3] = f2tf32(v.w);
        }
#pragma unroll
        for (int i = 0; i < 4; i++) {
            int idx = tid + i * 256;
            int kk = idx >> 5, n4 = idx & 31;
            float4 w = *reinterpret_cast<const float4*>(W + (size_t)(k0 + kk) * HH + n4 * 4);
            unsigned* p = &Ws[kk][n4 * 4];
            p[0] = f2tf32(w.x); p[1] = f2tf32(w.y); p[2] = f2tf32(w.z); p[3] = f2tf32(w.w);
        }
        __syncthreads();

#pragma unroll
        for (int k8 = 0; k8 < 4; k8++) {
            const int kk = k8 * 8;
            unsigned a[2][4], b[8][2];
#pragma unroll
            for (int mt = 0; mt < 2; mt++) {
                int r = wm * 32 + mt * 16;
                a[mt][0] = As[r + g][kk + t];
                a[mt][1] = As[r + g + 8][kk + t];
                a[mt][2] = As[r + g][kk + t + 4];
                a[mt][3] = As[r + g + 8][kk + t + 4];
            }
#pragma unroll
            for (int nt = 0; nt < 8; nt++) {
                int n = wn * 64 + nt * 8;
                b[nt][0] = Ws[kk + t][n + g];
                b[nt][1] = Ws[kk + t + 4][n + g];
            }
#pragma unroll
            for (int mt = 0; mt < 2; mt++)
#pragma unroll
                for (int nt = 0; nt < 8; nt++)
                    mma_tf32(acc[mt][nt], a[mt], b[nt]);
        }
        __syncthreads();
    }

    float csum[8][2];
#pragma unroll
    for (int nt = 0; nt < 8; nt++) { csum[nt][0] = 0.f; csum[nt][1] = 0.f; }

#pragma unroll
    for (int mt = 0; mt < 2; mt++) {
        int rr[2];
        rr[0] = row0 + wm * 32 + mt * 16 + g;
        rr[1] = rr[0] + 8;
#pragma unroll
        for (int half = 0; half < 2; half++) {
            int r = rr[half];
            if (r >= NN) continue;
            float iv = (OUTMODE == 2) ? __ldg(invdeg + r) : 1.0f;
#pragma unroll
            for (int nt = 0; nt < 8; nt++) {
                int col = wn * 64 + nt * 8 + 2 * t;
                float b0 = __ldg(bias + col), b1 = __ldg(bias + col + 1);
                float x0 = acc[mt][nt][half * 2 + 0] + b0;
                float x1 = acc[mt][nt][half * 2 + 1] + b1;
                if (LEAKY) {
                    x0 = (x0 >= 0.f) ? x0 : NEG_SLOPE * x0;
                    x1 = (x1 >= 0.f) ? x1 : NEG_SLOPE * x1;
                }
                csum[nt][0] += x0; csum[nt][1] += x1;
                if (OUTMODE == 2)
                    *reinterpret_cast<float2*>(C + (size_t)r * HH + col) = make_float2(x0, x1);
                if (OUTMODE == 1 || OUTMODE == 2) {
                    __nv_bfloat162 hb = __floats2bfloat162_rn(x0 * iv, x1 * iv);
                    *reinterpret_cast<__nv_bfloat162*>(Cb + (size_t)r * HH + col) = hb;
                }
            }
        }
    }

    __syncthreads();
#pragma unroll
    for (int nt = 0; nt < 8; nt++) {
#pragma unroll
        for (int c = 0; c < 2; c++) {
            float s = csum[nt][c];
            s += __shfl_xor_sync(0xffffffffu, s, 4);
            s += __shfl_xor_sync(0xffffffffu, s, 8);
            s += __shfl_xor_sync(0xffffffffu, s, 16);
            if (g == 0) atomicAdd(&colsm[wn * 64 + nt * 8 + 2 * t + c], s);
        }
    }
    __syncthreads();
    if (tid < HH) atomicAdd(&colsum[cs_off + tid], colsm[tid]);
}

// ---------------- final: column means -> Wpred -> Wcls -> softmax ----------------
__global__ void final_kernel(const float* __restrict__ colsum,
                             const float* __restrict__ Wpred, const float* __restrict__ bpred,
                             const float* __restrict__ Wcls, const float* __restrict__ bcls,
                             float* __restrict__ out) {
    __shared__ float cm[HH * (LL + 1)];
    __shared__ float gsh[HH];
    int tid = threadIdx.x;  // 128 threads
    for (int t = tid; t < HH * (LL + 1); t += 128) cm[t] = colsum[t] * (1.0f / (float)NN);
    __syncthreads();
    float g = bpred[tid];
    for (int k = 0; k < HH * (LL + 1); k++) g += cm[k] * Wpred[(size_t)k * HH + tid];
    gsh[tid] = g;
    __syncthreads();
    if (tid == 0) {
        float l0 = bcls[0], l1 = bcls[1];
        for (int j = 0; j < HH; j++) {
            l0 += gsh[j] * Wcls[j * 2 + 0];
            l1 += gsh[j] * Wcls[j * 2 + 1];
        }
        float m = fmaxf(l0, l1);
        float e0 = expf(l0 - m), e1 = expf(l1 - m);
        float inv = 1.0f / (e0 + e1);
        out[0] = e0 * inv;
        out[1] = e1 * inv;
    }
}

// ---------------- launch ----------------
extern "C" void kernel_launch(void* const* d_in, const int* in_sizes, int n_in,
                              void* d_out, int out_size) {
    const float* node_feat = (const float*)d_in[0];
    const float* degree    = (const float*)d_in[3];
    const float* Wn        = (const float*)d_in[4];
    const float* bn        = (const float*)d_in[5];
    const float* Wgcn      = (const float*)d_in[8];
    const float* bgcn      = (const float*)d_in[9];
    const float* Wpred     = (const float*)d_in[10];
    const float* bpred     = (const float*)d_in[11];
    const float* Wcls      = (const float*)d_in[12];
    const float* bcls      = (const float*)d_in[13];
    const int*   src       = (const int*)d_in[14];
    const int*   dst       = (const int*)d_in[15];
    float* out = (float*)d_out;

    float *p_cur, *p_agg, *p_inv, *p_cs;
    __nv_bfloat16 *p_h0b, *p_msgb;
    int *p_cnt, *p_pos, *p_rp, *p_col;
    cudaGetSymbolAddress((void**)&p_cur,  g_cur);
    cudaGetSymbolAddress((void**)&p_agg,  g_agg);
    cudaGetSymbolAddress((void**)&p_h0b,  g_h0b);
    cudaGetSymbolAddress((void**)&p_msgb, g_msgb);
    cudaGetSymbolAddress((void**)&p_inv,  g_invdeg);
    cudaGetSymbolAddress((void**)&p_cs,   g_colsum);
    cudaGetSymbolAddress((void**)&p_cnt,  g_cnt);
    cudaGetSymbolAddress((void**)&p_pos,  g_pos);
    cudaGetSymbolAddress((void**)&p_rp,   g_rowptr);
    cudaGetSymbolAddress((void**)&p_col,  g_col);

    const int gemm_blocks = (NN + 127) / 128;        // 391
    const int edge_blocks = (EE + 255) / 256;        // 3125
    const int node_blocks = (NN + 255) / 256;        // 196
    const int gath_blocks = (NN * 32 + 255) / 256;   // 6250

    // 1) init counters / invdeg / colsum
    init_kernel<<<node_blocks, 256>>>(degree, p_inv, p_cnt, p_pos, p_cs);

    // 2) CSR build (dst-major)
    hist_kernel<<<edge_blocks, 256>>>(dst, p_cnt);
    scan_kernel<<<1, 1024>>>(p_cnt, p_rp);
    fill_kernel<<<edge_blocks, 256>>>(src, dst, p_rp, p_pos, p_col);

    // 3) projection: h0b = bf16(node_feat @ Wn + bn) ; colsum[0:128]
    gemm_tc<NF, false, 1><<<gemm_blocks, 256>>>(node_feat, Wn, bn, nullptr, p_h0b,
                                                nullptr, p_cs, 0);

    // 4) fusion: cur[v] = sum_{u->v} h0b[u] ; msgb[v] = bf16(cur[v]*invdeg[v])
    gather_kernel<false, true><<<gath_blocks, 256>>>(p_h0b, nullptr, p_cur, p_msgb,
                                                     p_inv, p_rp, p_col);

    // 5) 3 GCN layers
    for (int l = 0; l < LL; l++) {
        // agg[v] = cur[v] + sum_{u->v} msgb[u]
        gather_kernel<true, false><<<gath_blocks, 256>>>(p_msgb, p_cur, p_agg, nullptr,
                                                         nullptr, p_rp, p_col);
        // cur = leaky(agg @ Wgcn + bgcn); msgb = bf16(cur*invdeg)  (last layer: colsum only)
        if (l < LL - 1)
            gemm_tc<HH, true, 2><<<gemm_blocks, 256>>>(p_agg, Wgcn, bgcn, p_cur, p_msgb,
                                                       p_inv, p_cs, (l + 1) * HH);
        else
            gemm_tc<HH, true, 0><<<gemm_blocks, 256>>>(p_agg, Wgcn, bgcn, nullptr, nullptr,
                                                       nullptr, p_cs, (l + 1) * HH);
    }

    // 6) readout
    final_kernel<<<1, 128>>>(p_cs, Wpred, bpred, Wcls, bcls, out);
}